// round 2
// baseline (speedup 1.0000x reference)
#include <cuda_runtime.h>

#define BB    8
#define TT_   384
#define HH    8
#define DH    64
#define CC    512
#define MROWS (BB*TT_)   // 3072
#define NTOK  2048

// scratch (allocation-free contract: __device__ globals)
__device__ float g_q[BB*HH*TT_*DH];   // [b,h,s,d]
__device__ float g_k[BB*HH*TT_*DH];   // [b,h,t,d]
__device__ float g_v[BB*HH*TT_*DH];   // [b,h,t,d]
__device__ float g_y[MROWS*CC];       // [b*T+s][h*64+d]
__device__ int   g_lo[MROWS];
__device__ int   g_hi[MROWS];

// ---------------------------------------------------------------------------
// Segment bounds: padpack_batch is sorted per b, so equal values are
// contiguous; each (b,s) attends exactly to [lo,hi).
__global__ void seg_kernel(const int* __restrict__ pb)
{
    int id = blockIdx.x * blockDim.x + threadIdx.x;
    if (id >= MROWS) return;
    int b = id / TT_, s = id % TT_;
    const int* row = pb + b * TT_;
    int v = row[s];
    int lo = s;     while (lo > 0   && row[lo-1] == v) lo--;
    int hi = s + 1; while (hi < TT_ && row[hi]   == v) hi++;
    g_lo[id] = lo;
    g_hi[id] = hi;
}

// ---------------------------------------------------------------------------
// Gathered QKV SGEMM: C[3072,1536] = X[pidx[m],:] @ [Wq|Wk|Wv]^T + bias
// 128x128 tile, BK=8, 256 threads, 8x8 per thread. Epilogue scatters into
// [b,h,s,d] layout.
__global__ __launch_bounds__(256) void qkv_gemm(
    const float* __restrict__ x,
    const float* __restrict__ Wq, const float* __restrict__ bq,
    const float* __restrict__ Wk, const float* __restrict__ bk,
    const float* __restrict__ Wv, const float* __restrict__ bv,
    const int*   __restrict__ pidx)
{
    __shared__ float As[8][132];
    __shared__ float Bs[8][132];

    const int m0  = blockIdx.x * 128;
    const int n0  = blockIdx.y * 128;       // 0..1535
    const int mat = n0 >> 9;                // 0=q,1=k,2=v (128 | 512)
    const int nc0 = n0 & 511;

    const float* W;  const float* bias;  float* ob;
    if      (mat == 0) { W = Wq; bias = bq; ob = g_q; }
    else if (mat == 1) { W = Wk; bias = bk; ob = g_k; }
    else               { W = Wv; bias = bv; ob = g_v; }

    const int tid  = threadIdx.x;
    const int arow = tid >> 1;              // 0..127
    const int akk  = (tid & 1) * 4;         // 0 or 4
    const int tx   = tid & 15;
    const int ty   = tid >> 4;

    const float* xrow = x + (size_t)pidx[m0 + arow] * CC + akk;
    const float* wrow = W + (size_t)(nc0 + arow) * CC + akk;

    float acc[8][8];
#pragma unroll
    for (int i = 0; i < 8; i++)
#pragma unroll
        for (int j = 0; j < 8; j++) acc[i][j] = 0.f;

    for (int k0 = 0; k0 < CC; k0 += 8) {
        float4 av = *(const float4*)(xrow + k0);
        float4 bw = *(const float4*)(wrow + k0);
        __syncthreads();
        As[akk+0][arow] = av.x; As[akk+1][arow] = av.y;
        As[akk+2][arow] = av.z; As[akk+3][arow] = av.w;
        Bs[akk+0][arow] = bw.x; Bs[akk+1][arow] = bw.y;
        Bs[akk+2][arow] = bw.z; Bs[akk+3][arow] = bw.w;
        __syncthreads();
#pragma unroll
        for (int kk = 0; kk < 8; kk++) {
            float a[8], bb[8];
            *(float4*)(a)    = *(const float4*)&As[kk][ty*4];
            *(float4*)(a+4)  = *(const float4*)&As[kk][64 + ty*4];
            *(float4*)(bb)   = *(const float4*)&Bs[kk][tx*4];
            *(float4*)(bb+4) = *(const float4*)&Bs[kk][64 + tx*4];
#pragma unroll
            for (int i = 0; i < 8; i++)
#pragma unroll
                for (int j = 0; j < 8; j++) acc[i][j] += a[i] * bb[j];
        }
    }

#pragma unroll
    for (int i = 0; i < 8; i++) {
        int rm = (i < 4) ? (ty*4 + i) : (64 + ty*4 + (i-4));
        int m  = m0 + rm;
        int b  = m / TT_, s = m % TT_;
#pragma unroll
        for (int j = 0; j < 8; j++) {
            int rn = (j < 4) ? (tx*4 + j) : (64 + tx*4 + (j-4));
            int n  = nc0 + rn;
            int h  = n >> 6, d = n & 63;
            ob[(((b*HH + h)*TT_) + s)*DH + d] = acc[i][j] + bias[n];
        }
    }
}

// ---------------------------------------------------------------------------
// Attention: one CTA per (b,s). relkeys/relvals rows are read once and shared
// across all 8 heads. Only the unmasked segment [lo,hi) is visited — exactly
// equivalent to the reference (masked exp(-1e9-max) underflows to 0 in fp32).
__global__ __launch_bounds__(128) void attn_kernel(
    const float* __restrict__ relk, const float* __restrict__ relv)
{
    const int id = blockIdx.x;              // b*T + s
    const int b  = id / TT_, s = id % TT_;
    const int lo = g_lo[id], hi = g_hi[id];
    const int L  = hi - lo;

    __shared__ float q_s[HH][DH];
    __shared__ float p_s[HH][TT_];

    const int tid = threadIdx.x, lane = tid & 31, w = tid >> 5;

    for (int i = tid; i < HH*DH; i += 128) {
        int h = i >> 6, d = i & 63;
        q_s[h][d] = g_q[((b*HH + h)*TT_ + s)*DH + d];
    }
    __syncthreads();

    const size_t rbase = ((size_t)(b*TT_ + s)) * TT_ * DH;

    // logits: warp computes one (h,t) dot at a time, lanes over d
    for (int idx = w; idx < HH * L; idx += 4) {
        int h  = idx / L, tt = idx - h * L;
        int t  = lo + tt;
        const float* kp = g_k + (size_t)((b*HH + h)*TT_ + t) * DH;
        const float* rp = relk + rbase + (size_t)t * DH;
        float a = q_s[h][lane]      * (kp[lane]      + rp[lane])
                + q_s[h][lane + 32] * (kp[lane + 32] + rp[lane + 32]);
#pragma unroll
        for (int o = 16; o; o >>= 1) a += __shfl_xor_sync(0xffffffffu, a, o);
        if (lane == 0) p_s[h][tt] = a * 0.125f;   // 1/sqrt(64)
    }
    __syncthreads();

    // softmax + AV per head: warp w owns heads 2w, 2w+1
#pragma unroll
    for (int hh = 0; hh < 2; hh++) {
        int h = 2*w + hh;
        float m = -1e30f;
        for (int tt = lane; tt < L; tt += 32) m = fmaxf(m, p_s[h][tt]);
#pragma unroll
        for (int o = 16; o; o >>= 1) m = fmaxf(m, __shfl_xor_sync(0xffffffffu, m, o));
        float sum = 0.f;
        for (int tt = lane; tt < L; tt += 32) {
            float e = __expf(p_s[h][tt] - m);
            p_s[h][tt] = e;
            sum += e;
        }
#pragma unroll
        for (int o = 16; o; o >>= 1) sum += __shfl_xor_sync(0xffffffffu, sum, o);
        float rinv = 1.0f / sum;

        const float* vb = g_v + (size_t)((b*HH + h)*TT_) * DH;
        float a0 = 0.f, a1 = 0.f;
        for (int tt = 0; tt < L; tt++) {
            int t = lo + tt;
            float p = p_s[h][tt];
            const float* rp = relv + rbase + (size_t)t * DH;
            a0 += p * (vb[t*DH + lane]      + rp[lane]);
            a1 += p * (vb[t*DH + lane + 32] + rp[lane + 32]);
        }
        g_y[(size_t)id*CC + h*DH + lane]      = a0 * rinv;
        g_y[(size_t)id*CC + h*DH + lane + 32] = a1 * rinv;
    }
}

// ---------------------------------------------------------------------------
// Output projection with inverse-index row gather: only the 2048 needed rows
// are projected. out[i,:] = g_y[inv[i],:] @ Wp^T + bp
// 64x64 tile, BK=16, 256 threads, 4x4 per thread.
__global__ __launch_bounds__(256) void out_gemm(
    const float* __restrict__ Wp, const float* __restrict__ bp,
    const int*   __restrict__ inv, float* __restrict__ out)
{
    __shared__ float As[16][68];
    __shared__ float Bs[16][68];

    const int m0 = blockIdx.x * 64;
    const int n0 = blockIdx.y * 64;
    const int tid  = threadIdx.x;
    const int arow = tid >> 2;             // 0..63
    const int akk  = (tid & 3) * 4;        // 0,4,8,12
    const int tx   = tid & 15;
    const int ty   = tid >> 4;

    const float* yrow = g_y + (size_t)inv[m0 + arow] * CC + akk;
    const float* wrow = Wp  + (size_t)(n0 + arow) * CC + akk;

    float acc[4][4];
#pragma unroll
    for (int i = 0; i < 4; i++)
#pragma unroll
        for (int j = 0; j < 4; j++) acc[i][j] = 0.f;

    for (int k0 = 0; k0 < CC; k0 += 16) {
        float4 av = *(const float4*)(yrow + k0);
        float4 bw = *(const float4*)(wrow + k0);
        __syncthreads();
        As[akk+0][arow] = av.x; As[akk+1][arow] = av.y;
        As[akk+2][arow] = av.z; As[akk+3][arow] = av.w;
        Bs[akk+0][arow] = bw.x; Bs[akk+1][arow] = bw.y;
        Bs[akk+2][arow] = bw.z; Bs[akk+3][arow] = bw.w;
        __syncthreads();
#pragma unroll
        for (int kk = 0; kk < 16; kk++) {
            float a[4], bb[4];
            *(float4*)a  = *(const float4*)&As[kk][ty*4];
            *(float4*)bb = *(const float4*)&Bs[kk][tx*4];
#pragma unroll
            for (int i = 0; i < 4; i++)
#pragma unroll
                for (int j = 0; j < 4; j++) acc[i][j] += a[i] * bb[j];
        }
    }

#pragma unroll
    for (int i = 0; i < 4; i++) {
        int m = m0 + ty*4 + i;
#pragma unroll
        for (int j = 0; j < 4; j++) {
            int n = n0 + tx*4 + j;
            out[(size_t)m*CC + n] = acc[i][j] + bp[n];
        }
    }
}

// ---------------------------------------------------------------------------
extern "C" void kernel_launch(void* const* d_in, const int* in_sizes, int n_in,
                              void* d_out, int out_size)
{
    const float* x    = (const float*)d_in[0];
    const float* relk = (const float*)d_in[1];
    const float* relv = (const float*)d_in[2];
    const float* Wq   = (const float*)d_in[3];
    const float* bq   = (const float*)d_in[4];
    const float* Wk   = (const float*)d_in[5];
    const float* bk   = (const float*)d_in[6];
    const float* Wv   = (const float*)d_in[7];
    const float* bv   = (const float*)d_in[8];
    const float* Wp   = (const float*)d_in[9];
    const float* bp   = (const float*)d_in[10];
    const int*   pidx = (const int*)d_in[11];
    const int*   pb   = (const int*)d_in[12];
    const int*   inv  = (const int*)d_in[13];
    float*       out  = (float*)d_out;

    seg_kernel<<<(MROWS + 255) / 256, 256>>>(pb);
    qkv_gemm<<<dim3(24, 12), 256>>>(x, Wq, bq, Wk, bk, Wv, bv, pidx);
    attn_kernel<<<MROWS, 128>>>(relk, relv);
    out_gemm<<<dim3(32, 8), 256>>>(Wp, bp, inv, out);
}

// round 5
// speedup vs baseline: 1.2923x; 1.2923x over previous
#include <cuda_runtime.h>
#include <cuda_bf16.h>
#include <cstdint>

#define BB    8
#define TT_   384
#define HH    8
#define DH    64
#define CC    512
#define MROWS (BB*TT_)   // 3072 slots
#define NTOK  2048
#define KEFF  1024       // hi(512) | lo(512) storage per row
#define NIT   48         // 3 segments x 16 iters of BK=32 (K_eff = 1536)

// ------------------------- scratch (__device__ globals) ---------------------
__device__ __align__(256) __nv_bfloat16 g_xs[NTOK*KEFF];     // x split hi|lo
__device__ __align__(256) __nv_bfloat16 g_ws[3*CC*KEFF];     // Wq|Wk|Wv split
__device__ __align__(256) __nv_bfloat16 g_wps[CC*KEFF];      // Wp split
__device__ __align__(256) __nv_bfloat16 g_ys[MROWS*KEFF];    // attention out split
__device__ float g_q0[NTOK*3*CC];                            // [tok][q512|k512|v512]
__device__ int   g_lo[MROWS];
__device__ int   g_hi[MROWS];

// ------------------------- mma helper ---------------------------------------
#define MMA16816(d, a, b) \
    asm volatile("mma.sync.aligned.m16n8k16.row.col.f32.bf16.bf16.f32 " \
        "{%0,%1,%2,%3}, {%4,%5,%6,%7}, {%8,%9}, {%0,%1,%2,%3};" \
        : "+f"((d)[0]), "+f"((d)[1]), "+f"((d)[2]), "+f"((d)[3]) \
        : "r"((a)[0]), "r"((a)[1]), "r"((a)[2]), "r"((a)[3]), \
          "r"((b)[0]), "r"((b)[1]))

// ------------------------- conversion kernels -------------------------------
__device__ __forceinline__ void split4_store(float4 v, __nv_bfloat16* hi, __nv_bfloat16* lo) {
    __nv_bfloat16 h0 = __float2bfloat16(v.x), h1 = __float2bfloat16(v.y);
    __nv_bfloat16 h2 = __float2bfloat16(v.z), h3 = __float2bfloat16(v.w);
    __nv_bfloat16 l0 = __float2bfloat16(v.x - __bfloat162float(h0));
    __nv_bfloat16 l1 = __float2bfloat16(v.y - __bfloat162float(h1));
    __nv_bfloat16 l2 = __float2bfloat16(v.z - __bfloat162float(h2));
    __nv_bfloat16 l3 = __float2bfloat16(v.w - __bfloat162float(h3));
    __nv_bfloat162 H0, H1, L0, L1;
    H0.x = h0; H0.y = h1; H1.x = h2; H1.y = h3;
    L0.x = l0; L0.y = l1; L1.x = l2; L1.y = l3;
    uint2 uh, ul;
    uh.x = *reinterpret_cast<uint32_t*>(&H0); uh.y = *reinterpret_cast<uint32_t*>(&H1);
    ul.x = *reinterpret_cast<uint32_t*>(&L0); ul.y = *reinterpret_cast<uint32_t*>(&L1);
    *reinterpret_cast<uint2*>(hi) = uh;
    *reinterpret_cast<uint2*>(lo) = ul;
}

// split x [2048x512] into g_xs [2048 x (512hi|512lo)]
__global__ void conv_x(const float* __restrict__ x)
{
    int i = blockIdx.x * blockDim.x + threadIdx.x;   // 2048*128 float4s
    int m = i >> 7, f4 = i & 127;
    float4 v = *reinterpret_cast<const float4*>(x + (size_t)m * CC + f4 * 4);
    split4_store(v, g_xs + (size_t)m * KEFF + f4 * 4,
                    g_xs + (size_t)m * KEFF + 512 + f4 * 4);
}

// split one [512x512] weight; which==0 -> g_ws at row0, which==1 -> g_wps
__global__ void conv_w(const float* __restrict__ src, int row0, int which)
{
    int i = blockIdx.x * blockDim.x + threadIdx.x;   // 512*128 float4s
    int r = i >> 7, f4 = i & 127;
    float4 v = *reinterpret_cast<const float4*>(src + (size_t)r * CC + f4 * 4);
    __nv_bfloat16* dst = which ? g_wps : g_ws;
    size_t base = (size_t)(row0 + r) * KEFF + f4 * 4;
    split4_store(v, dst + base, dst + base + 512);
}

// ------------------------- segment bounds -----------------------------------
__global__ void seg_kernel(const int* __restrict__ pb)
{
    int id = blockIdx.x * blockDim.x + threadIdx.x;
    if (id >= MROWS) return;
    int b = id / TT_, s = id % TT_;
    const int* row = pb + b * TT_;
    int v = row[s];
    int lo = s;     while (lo > 0   && row[lo-1] == v) lo--;
    int hi = s + 1; while (hi < TT_ && row[hi]   == v) hi++;
    g_lo[id] = lo;
    g_hi[id] = hi;
}

// ------------------------- HMMA GEMM core (shared by both GEMMs) ------------
// C[m0:128, n0:128] = A(hi|lo)[.,1024] x B(hi|lo)[.,1024]^T over K_eff=1536
// 256 threads = 8 warps (2 M x 4 N), warp tile 64x32, m16n8k16 bf16 HMMA.
struct GemmAcc { float a[4][4][4]; };

__device__ __forceinline__ void gemm_core(
    const __nv_bfloat16* __restrict__ aRow,   // this thread's A row ptr (+ac)
    const __nv_bfloat16* __restrict__ bRow,   // this thread's B row ptr (+ac)
    __nv_bfloat16 (*As)[128][40], __nv_bfloat16 (*Bs)[128][40],
    GemmAcc& acc)
{
    const int tid  = threadIdx.x;
    const int lane = tid & 31, wid = tid >> 5;
    const int wm = wid >> 2, wn = wid & 3;
    const int arow = tid >> 1, ac = (tid & 1) * 16;

#pragma unroll
    for (int mi = 0; mi < 4; mi++)
#pragma unroll
        for (int nj = 0; nj < 4; nj++)
#pragma unroll
            for (int r = 0; r < 4; r++) acc.a[mi][nj][r] = 0.f;

    // preload iter 0 (seg 0, k 0)
    uint4 va0 = *reinterpret_cast<const uint4*>(aRow);
    uint4 va1 = *reinterpret_cast<const uint4*>(aRow + 8);
    uint4 vb0 = *reinterpret_cast<const uint4*>(bRow);
    uint4 vb1 = *reinterpret_cast<const uint4*>(bRow + 8);
    *reinterpret_cast<uint4*>(&As[0][arow][ac])     = va0;
    *reinterpret_cast<uint4*>(&As[0][arow][ac + 8]) = va1;
    *reinterpret_cast<uint4*>(&Bs[0][arow][ac])     = vb0;
    *reinterpret_cast<uint4*>(&Bs[0][arow][ac + 8]) = vb1;
    __syncthreads();

    for (int it = 0; it < NIT; ++it) {
        const int buf = it & 1;
        const bool has_next = (it + 1) < NIT;
        if (has_next) {
            int nit = it + 1;
            int seg = nit >> 4;
            int ka  = ((seg == 2) ? 512 : 0) + (nit & 15) * 32;
            int kb  = ((seg == 1) ? 512 : 0) + (nit & 15) * 32;
            va0 = *reinterpret_cast<const uint4*>(aRow + ka);
            va1 = *reinterpret_cast<const uint4*>(aRow + ka + 8);
            vb0 = *reinterpret_cast<const uint4*>(bRow + kb);
            vb1 = *reinterpret_cast<const uint4*>(bRow + kb + 8);
        }
#pragma unroll
        for (int kk = 0; kk < 2; ++kk) {
            uint32_t af[4][4], bf[4][2];
#pragma unroll
            for (int mi = 0; mi < 4; mi++) {
                const __nv_bfloat16* ap =
                    &As[buf][wm*64 + mi*16 + (lane >> 2)][kk*16 + (lane & 3)*2];
                af[mi][0] = *reinterpret_cast<const uint32_t*>(ap);
                af[mi][1] = *reinterpret_cast<const uint32_t*>(ap + 8*40);
                af[mi][2] = *reinterpret_cast<const uint32_t*>(ap + 8);
                af[mi][3] = *reinterpret_cast<const uint32_t*>(ap + 8*40 + 8);
            }
#pragma unroll
            for (int nj = 0; nj < 4; nj++) {
                const __nv_bfloat16* bp =
                    &Bs[buf][wn*32 + nj*8 + (lane >> 2)][kk*16 + (lane & 3)*2];
                bf[nj][0] = *reinterpret_cast<const uint32_t*>(bp);
                bf[nj][1] = *reinterpret_cast<const uint32_t*>(bp + 8);
            }
#pragma unroll
            for (int mi = 0; mi < 4; mi++)
#pragma unroll
                for (int nj = 0; nj < 4; nj++)
                    MMA16816(acc.a[mi][nj], af[mi], bf[nj]);
        }
        if (has_next) {
            const int nbuf = buf ^ 1;
            *reinterpret_cast<uint4*>(&As[nbuf][arow][ac])     = va0;
            *reinterpret_cast<uint4*>(&As[nbuf][arow][ac + 8]) = va1;
            *reinterpret_cast<uint4*>(&Bs[nbuf][arow][ac])     = vb0;
            *reinterpret_cast<uint4*>(&Bs[nbuf][arow][ac + 8]) = vb1;
        }
        __syncthreads();
    }
}

// ------------------------- QKV GEMM -----------------------------------------
// g_q0[2048,1536] = g_xs x g_ws^T + [bq|bk|bv]
__global__ __launch_bounds__(256) void qkv_mma(
    const float* __restrict__ bq, const float* __restrict__ bk,
    const float* __restrict__ bv)
{
    __shared__ __nv_bfloat16 As[2][128][40];
    __shared__ __nv_bfloat16 Bs[2][128][40];
    const int tid = threadIdx.x;
    const int lane = tid & 31, wid = tid >> 5;
    const int wm = wid >> 2, wn = wid & 3;
    const int m0 = blockIdx.x * 128, n0 = blockIdx.y * 128;
    const int arow = tid >> 1, ac = (tid & 1) * 16;

    const __nv_bfloat16* aRow = g_xs + (size_t)(m0 + arow) * KEFF + ac;
    const __nv_bfloat16* bRow = g_ws + (size_t)(n0 + arow) * KEFF + ac;

    GemmAcc acc;
    gemm_core(aRow, bRow, As, Bs, acc);

    const int mat = n0 >> 9;
    const float* bias = (mat == 0) ? bq : (mat == 1) ? bk : bv;

#pragma unroll
    for (int mi = 0; mi < 4; mi++) {
        int r = m0 + wm*64 + mi*16 + (lane >> 2);
#pragma unroll
        for (int nj = 0; nj < 4; nj++) {
            int cI = n0 + wn*32 + nj*8 + (lane & 3)*2;
            float b0v = bias[(cI & 511)], b1v = bias[(cI & 511) + 1];
            float2 v0 = { acc.a[mi][nj][0] + b0v, acc.a[mi][nj][1] + b1v };
            float2 v1 = { acc.a[mi][nj][2] + b0v, acc.a[mi][nj][3] + b1v };
            *reinterpret_cast<float2*>(g_q0 + (size_t)r * 1536 + cI)       = v0;
            *reinterpret_cast<float2*>(g_q0 + (size_t)(r + 8) * 1536 + cI) = v1;
        }
    }
}

// ------------------------- OUT GEMM -----------------------------------------
// out[2048,512] = g_ys[inv[m],:] x g_wps^T + bp
__global__ __launch_bounds__(256) void out_mma(
    const float* __restrict__ bp, const int* __restrict__ inv,
    float* __restrict__ out)
{
    __shared__ __nv_bfloat16 As[2][128][40];
    __shared__ __nv_bfloat16 Bs[2][128][40];
    const int tid = threadIdx.x;
    const int lane = tid & 31, wid = tid >> 5;
    const int wm = wid >> 2, wn = wid & 3;
    const int m0 = blockIdx.x * 128, n0 = blockIdx.y * 128;
    const int arow = tid >> 1, ac = (tid & 1) * 16;

    const __nv_bfloat16* aRow = g_ys + (size_t)inv[m0 + arow] * KEFF + ac;
    const __nv_bfloat16* bRow = g_wps + (size_t)(n0 + arow) * KEFF + ac;

    GemmAcc acc;
    gemm_core(aRow, bRow, As, Bs, acc);

#pragma unroll
    for (int mi = 0; mi < 4; mi++) {
        int r = m0 + wm*64 + mi*16 + (lane >> 2);
#pragma unroll
        for (int nj = 0; nj < 4; nj++) {
            int cI = n0 + wn*32 + nj*8 + (lane & 3)*2;
            float b0v = bp[cI], b1v = bp[cI + 1];
            float2 v0 = { acc.a[mi][nj][0] + b0v, acc.a[mi][nj][1] + b1v };
            float2 v1 = { acc.a[mi][nj][2] + b0v, acc.a[mi][nj][3] + b1v };
            *reinterpret_cast<float2*>(out + (size_t)r * CC + cI)       = v0;
            *reinterpret_cast<float2*>(out + (size_t)(r + 8) * CC + cI) = v1;
        }
    }
}

// ------------------------- attention (fp32) ---------------------------------
// q/k/v live in g_q0 rows indexed via pidx (per-token projection).
__global__ __launch_bounds__(128) void attn_kernel(
    const float* __restrict__ relk, const float* __restrict__ relv,
    const int* __restrict__ pidx)
{
    const int id = blockIdx.x;              // b*T + s
    const int b  = id / TT_, s = id % TT_;
    const int lo = g_lo[id], hi = g_hi[id];
    const int L  = hi - lo;

    __shared__ float q_s[HH][DH];
    __shared__ float p_s[HH][TT_];
    __shared__ int   tok_sh[TT_];

    const int tid = threadIdx.x, lane = tid & 31, w = tid >> 5;
    const int tok_s = pidx[id];

    for (int i = tid; i < TT_; i += 128) tok_sh[i] = pidx[b * TT_ + i];
    for (int i = tid; i < HH*DH; i += 128)
        q_s[i >> 6][i & 63] = g_q0[(size_t)tok_s * 1536 + i];
    __syncthreads();

    const size_t rbase = ((size_t)(b*TT_ + s)) * TT_ * DH;

    for (int idx = w; idx < HH * L; idx += 4) {
        int h  = idx / L, tt = idx - h * L;
        int t  = lo + tt;
        const float* kp = g_q0 + (size_t)tok_sh[t] * 1536 + 512 + h * DH;
        const float* rp = relk + rbase + (size_t)t * DH;
        float a = q_s[h][lane]      * (kp[lane]      + rp[lane])
                + q_s[h][lane + 32] * (kp[lane + 32] + rp[lane + 32]);
#pragma unroll
        for (int o = 16; o; o >>= 1) a += __shfl_xor_sync(0xffffffffu, a, o);
        if (lane == 0) p_s[h][tt] = a * 0.125f;   // 1/sqrt(64)
    }
    __syncthreads();

#pragma unroll
    for (int hh = 0; hh < 2; hh++) {
        int h = 2*w + hh;
        float m = -1e30f;
        for (int tt = lane; tt < L; tt += 32) m = fmaxf(m, p_s[h][tt]);
#pragma unroll
        for (int o = 16; o; o >>= 1) m = fmaxf(m, __shfl_xor_sync(0xffffffffu, m, o));
        float sum = 0.f;
        for (int tt = lane; tt < L; tt += 32) {
            float e = __expf(p_s[h][tt] - m);
            p_s[h][tt] = e;
            sum += e;
        }
#pragma unroll
        for (int o = 16; o; o >>= 1) sum += __shfl_xor_sync(0xffffffffu, sum, o);
        float rinv = 1.0f / sum;

        float a0 = 0.f, a1 = 0.f;
        for (int tt = 0; tt < L; tt++) {
            int t = lo + tt;
            float p = p_s[h][tt];
            const float* vp = g_q0 + (size_t)tok_sh[t] * 1536 + 1024 + h * DH;
            const float* rp = relv + rbase + (size_t)t * DH;
            a0 += p * (vp[lane]      + rp[lane]);
            a1 += p * (vp[lane + 32] + rp[lane + 32]);
        }
        float o0 = a0 * rinv, o1 = a1 * rinv;
        size_t yb = (size_t)id * KEFF + h * DH;
        __nv_bfloat16 h0 = __float2bfloat16(o0);
        __nv_bfloat16 h1 = __float2bfloat16(o1);
        g_ys[yb + lane]            = h0;
        g_ys[yb + 512 + lane]      = __float2bfloat16(o0 - __bfloat162float(h0));
        g_ys[yb + lane + 32]       = h1;
        g_ys[yb + 512 + lane + 32] = __float2bfloat16(o1 - __bfloat162float(h1));
    }
}

// ---------------------------------------------------------------------------
extern "C" void kernel_launch(void* const* d_in, const int* in_sizes, int n_in,
                              void* d_out, int out_size)
{
    const float* x    = (const float*)d_in[0];
    const float* relk = (const float*)d_in[1];
    const float* relv = (const float*)d_in[2];
    const float* Wq   = (const float*)d_in[3];
    const float* bq   = (const float*)d_in[4];
    const float* Wk   = (const float*)d_in[5];
    const float* bk   = (const float*)d_in[6];
    const float* Wv   = (const float*)d_in[7];
    const float* bv   = (const float*)d_in[8];
    const float* Wp   = (const float*)d_in[9];
    const float* bp   = (const float*)d_in[10];
    const int*   pidx = (const int*)d_in[11];
    const int*   pb   = (const int*)d_in[12];
    const int*   inv  = (const int*)d_in[13];
    float*       out  = (float*)d_out;

    conv_x<<<NTOK*128/256, 256>>>(x);
    conv_w<<<CC*128/256, 256>>>(Wq, 0,    0);
    conv_w<<<CC*128/256, 256>>>(Wk, 512,  0);
    conv_w<<<CC*128/256, 256>>>(Wv, 1024, 0);
    conv_w<<<CC*128/256, 256>>>(Wp, 0,    1);
    seg_kernel<<<(MROWS + 255) / 256, 256>>>(pb);
    qkv_mma<<<dim3(16, 12), 256>>>(bq, bk, bv);
    attn_kernel<<<MROWS, 128>>>(relk, relv, pidx);
    out_mma<<<dim3(16, 4), 256>>>(bp, inv, out);
}

// round 8
// speedup vs baseline: 1.4086x; 1.0900x over previous
#include <cuda_runtime.h>
#include <cuda_bf16.h>
#include <cstdint>

#define BB    8
#define TT_   384
#define HH    8
#define DH    64
#define CC    512
#define MROWS (BB*TT_)   // 3072 slots
#define NTOK  2048
#define KEFF  1024       // hi(512) | lo(512) per row
#define NIT   48         // 3 segments x 16 iters of BK=32

// ------------------------- scratch ------------------------------------------
__device__ __align__(256) __nv_bfloat16 g_xs[NTOK*KEFF];
__device__ __align__(256) __nv_bfloat16 g_ws[3*CC*KEFF];
__device__ __align__(256) __nv_bfloat16 g_wps[CC*KEFF];
__device__ __align__(256) __nv_bfloat16 g_ys[MROWS*KEFF];
__device__ float g_q0[NTOK*3*CC];     // [tok][q512|k512|v512]
__device__ int   g_lo[MROWS];
__device__ int   g_hi[MROWS];

// ------------------------- asm helpers --------------------------------------
__device__ __forceinline__ uint32_t smem_u32(const void* p) {
    uint32_t a;
    asm("{ .reg .u64 t; cvta.to.shared.u64 t, %1; cvt.u32.u64 %0, t; }" : "=r"(a) : "l"(p));
    return a;
}
#define MMA16816(d, a, b) \
    asm volatile("mma.sync.aligned.m16n8k16.row.col.f32.bf16.bf16.f32 " \
        "{%0,%1,%2,%3}, {%4,%5,%6,%7}, {%8,%9}, {%0,%1,%2,%3};" \
        : "+f"((d)[0]), "+f"((d)[1]), "+f"((d)[2]), "+f"((d)[3]) \
        : "r"((a)[0]), "r"((a)[1]), "r"((a)[2]), "r"((a)[3]), \
          "r"((b)[0]), "r"((b)[1]))
#define LDSM4(r0,r1,r2,r3,addr) \
    asm volatile("ldmatrix.sync.aligned.m8n8.x4.shared.b16 {%0,%1,%2,%3}, [%4];" \
        : "=r"(r0), "=r"(r1), "=r"(r2), "=r"(r3) : "r"(addr))
#define CPASYNC16(dst, src) \
    asm volatile("cp.async.cg.shared.global [%0], [%1], 16;" :: "r"(dst), "l"(src))
#define CPCOMMIT()  asm volatile("cp.async.commit_group;" ::: "memory")
#define CPWAIT2()   asm volatile("cp.async.wait_group 2;" ::: "memory")

// seg/k offsets for split passes: AhiBhi, AhiBlo, AloBhi
__device__ __forceinline__ void split_offs(int it, int& kA, int& kB) {
    int seg = it >> 4;
    kA = ((seg == 2) ? 512 : 0) + (it & 15) * 32;
    kB = ((seg == 1) ? 512 : 0) + (it & 15) * 32;
}

// ------------------------- fused conversion ---------------------------------
__device__ __forceinline__ void split4_store(float4 v, __nv_bfloat16* hi, __nv_bfloat16* lo) {
    __nv_bfloat16 h0 = __float2bfloat16(v.x), h1 = __float2bfloat16(v.y);
    __nv_bfloat16 h2 = __float2bfloat16(v.z), h3 = __float2bfloat16(v.w);
    __nv_bfloat16 l0 = __float2bfloat16(v.x - __bfloat162float(h0));
    __nv_bfloat16 l1 = __float2bfloat16(v.y - __bfloat162float(h1));
    __nv_bfloat16 l2 = __float2bfloat16(v.z - __bfloat162float(h2));
    __nv_bfloat16 l3 = __float2bfloat16(v.w - __bfloat162float(h3));
    __nv_bfloat162 H0, H1, L0, L1;
    H0.x = h0; H0.y = h1; H1.x = h2; H1.y = h3;
    L0.x = l0; L0.y = l1; L1.x = l2; L1.y = l3;
    uint2 uh, ul;
    uh.x = *reinterpret_cast<uint32_t*>(&H0); uh.y = *reinterpret_cast<uint32_t*>(&H1);
    ul.x = *reinterpret_cast<uint32_t*>(&L0); ul.y = *reinterpret_cast<uint32_t*>(&L1);
    *reinterpret_cast<uint2*>(hi) = uh;
    *reinterpret_cast<uint2*>(lo) = ul;
}

__global__ void conv_all(const float* __restrict__ x,
                         const float* __restrict__ Wq, const float* __restrict__ Wk,
                         const float* __restrict__ Wv, const float* __restrict__ Wp)
{
    int i = blockIdx.x * blockDim.x + threadIdx.x;   // (2048 + 4*512) * 128
    int m = i >> 7, f4 = i & 127;
    const float* src;
    __nv_bfloat16* dsthi;
    if (m < NTOK) {
        src = x + (size_t)m * CC;
        dsthi = g_xs + (size_t)m * KEFF;
    } else {
        int r = m - NTOK;
        int w = r >> 9, rr = r & 511;
        src = (w == 0 ? Wq : w == 1 ? Wk : w == 2 ? Wv : Wp) + (size_t)rr * CC;
        dsthi = (w < 3) ? g_ws + (size_t)(w * 512 + rr) * KEFF
                        : g_wps + (size_t)rr * KEFF;
    }
    float4 v = reinterpret_cast<const float4*>(src)[f4];
    split4_store(v, dsthi + f4 * 4, dsthi + 512 + f4 * 4);
}

// ------------------------- segment bounds -----------------------------------
__global__ void seg_kernel(const int* __restrict__ pb)
{
    int id = blockIdx.x * blockDim.x + threadIdx.x;
    if (id >= MROWS) return;
    int b = id / TT_, s = id % TT_;
    const int* row = pb + b * TT_;
    int v = row[s];
    int lo = s;     while (lo > 0   && row[lo-1] == v) lo--;
    int hi = s + 1; while (hi < TT_ && row[hi]   == v) hi++;
    g_lo[id] = lo;
    g_hi[id] = hi;
}

// ------------------------- QKV GEMM (128x128, 4-stage cp.async) -------------
// smem: A 4 stages x 128x40 bf16 (10240B each), then B 4 x 128x40.
#define ASTB 10240
#define QKV_SMEM (8*ASTB)

__global__ __launch_bounds__(256) void qkv_mma(
    const float* __restrict__ bq, const float* __restrict__ bk,
    const float* __restrict__ bv)
{
    extern __shared__ __align__(128) char smem[];
    const uint32_t sbA = smem_u32(smem);
    const uint32_t sbB = sbA + 4*ASTB;

    const int tid = threadIdx.x;
    const int lane = tid & 31, wid = tid >> 5;
    const int wm = wid >> 2, wn = wid & 3;
    const int m0 = blockIdx.x * 128, n0 = blockIdx.y * 128;

    // cp.async per-thread mapping: row = tid>>1, col base = (tid&1)*16
    const int crow = tid >> 1, cb = (tid & 1) * 16;
    const __nv_bfloat16* aG = g_xs + (size_t)(m0 + crow) * KEFF + cb;
    const __nv_bfloat16* bG = g_ws + (size_t)(n0 + crow) * KEFF + cb;
    const uint32_t dA = sbA + (uint32_t)(crow * 40 + cb) * 2;
    const uint32_t dB = sbB + (uint32_t)(crow * 40 + cb) * 2;

    float acc[4][4][4];
#pragma unroll
    for (int mi = 0; mi < 4; mi++)
#pragma unroll
        for (int nj = 0; nj < 4; nj++)
#pragma unroll
            for (int r = 0; r < 4; r++) acc[mi][nj][r] = 0.f;

    // prologue: stages 0..2
#pragma unroll
    for (int p = 0; p < 3; p++) {
        int kA, kB; split_offs(p, kA, kB);
        uint32_t oA = dA + p*ASTB, oB = dB + p*ASTB;
        CPASYNC16(oA,      aG + kA);
        CPASYNC16(oA + 16, aG + kA + 8);
        CPASYNC16(oB,      bG + kB);
        CPASYNC16(oB + 16, bG + kB + 8);
        CPCOMMIT();
    }

    // fragment lane addressing
    const uint32_t frow = (lane & 15), fcol = (lane >> 4) * 8;

    for (int it = 0; it < NIT; ++it) {
        CPWAIT2();
        __syncthreads();
        // issue stage it+3 (into buf (it-1)&3, consumed last iter by all warps)
        if (it + 3 < NIT) {
            int nst = it + 3, kA, kB; split_offs(nst, kA, kB);
            uint32_t oA = dA + (nst & 3)*ASTB, oB = dB + (nst & 3)*ASTB;
            CPASYNC16(oA,      aG + kA);
            CPASYNC16(oA + 16, aG + kA + 8);
            CPASYNC16(oB,      bG + kB);
            CPASYNC16(oB + 16, bG + kB + 8);
        }
        CPCOMMIT();   // unconditional: keeps 3 groups pending so wait_group 2 == stage ready

        const uint32_t aS = sbA + (it & 3)*ASTB;
        const uint32_t bS = sbB + (it & 3)*ASTB;
#pragma unroll
        for (int kk = 0; kk < 2; ++kk) {
            uint32_t af[4][4], br[2][4];
            const uint32_t cOff = (kk*16 + fcol) * 2;
#pragma unroll
            for (int mi = 0; mi < 4; mi++) {
                uint32_t ad = aS + (uint32_t)((wm*64 + mi*16 + frow) * 40) * 2 + cOff;
                LDSM4(af[mi][0], af[mi][1], af[mi][2], af[mi][3], ad);
            }
#pragma unroll
            for (int p = 0; p < 2; p++) {
                uint32_t bd = bS + (uint32_t)((wn*32 + p*16 + frow) * 40) * 2 + cOff;
                LDSM4(br[p][0], br[p][1], br[p][2], br[p][3], bd);
            }
#pragma unroll
            for (int mi = 0; mi < 4; mi++)
#pragma unroll
                for (int nj = 0; nj < 4; nj++) {
                    uint32_t bf[2] = { br[nj>>1][nj & 1], br[nj>>1][2 + (nj & 1)] };
                    MMA16816(acc[mi][nj], af[mi], bf);
                }
        }
    }

    const int mat = n0 >> 9;
    const float* bias = (mat == 0) ? bq : (mat == 1) ? bk : bv;
#pragma unroll
    for (int mi = 0; mi < 4; mi++) {
        int r = m0 + wm*64 + mi*16 + (lane >> 2);
#pragma unroll
        for (int nj = 0; nj < 4; nj++) {
            int cI = n0 + wn*32 + nj*8 + (lane & 3)*2;
            float b0v = bias[cI & 511], b1v = bias[(cI & 511) + 1];
            float2 v0 = { acc[mi][nj][0] + b0v, acc[mi][nj][1] + b1v };
            float2 v1 = { acc[mi][nj][2] + b0v, acc[mi][nj][3] + b1v };
            *reinterpret_cast<float2*>(g_q0 + (size_t)r * 1536 + cI)       = v0;
            *reinterpret_cast<float2*>(g_q0 + (size_t)(r + 8) * 1536 + cI) = v1;
        }
    }
}

// ------------------------- OUT GEMM (64x128 tile, 128 CTAs) -----------------
#define ASTB64 5120
#define OUT_SMEM (4*ASTB64 + 4*ASTB)

__global__ __launch_bounds__(256) void out_mma(
    const float* __restrict__ bp, const int* __restrict__ inv,
    float* __restrict__ out)
{
    extern __shared__ __align__(128) char smem[];
    const uint32_t sbA = smem_u32(smem);
    const uint32_t sbB = sbA + 4*ASTB64;

    const int tid = threadIdx.x;
    const int lane = tid & 31, wid = tid >> 5;
    const int wm = wid >> 2, wn = wid & 3;
    const int m0 = blockIdx.x * 64, n0 = blockIdx.y * 128;

    // A: 64 rows, 1 chunk/thread: row = tid>>2, col = (tid&3)*8
    const int arw = tid >> 2, acb = (tid & 3) * 8;
    const __nv_bfloat16* aG = g_ys + (size_t)inv[m0 + arw] * KEFF + acb;
    const uint32_t dA = sbA + (uint32_t)(arw * 40 + acb) * 2;
    // B: 128 rows, 2 chunks/thread
    const int brw = tid >> 1, bcb = (tid & 1) * 16;
    const __nv_bfloat16* bG = g_wps + (size_t)(n0 + brw) * KEFF + bcb;
    const uint32_t dB = sbB + (uint32_t)(brw * 40 + bcb) * 2;

    float acc[2][4][4];
#pragma unroll
    for (int mi = 0; mi < 2; mi++)
#pragma unroll
        for (int nj = 0; nj < 4; nj++)
#pragma unroll
            for (int r = 0; r < 4; r++) acc[mi][nj][r] = 0.f;

#pragma unroll
    for (int p = 0; p < 3; p++) {
        int kA, kB; split_offs(p, kA, kB);
        CPASYNC16(dA + p*ASTB64, aG + kA);
        uint32_t oB = dB + p*ASTB;
        CPASYNC16(oB,      bG + kB);
        CPASYNC16(oB + 16, bG + kB + 8);
        CPCOMMIT();
    }

    const uint32_t frow = (lane & 15), fcol = (lane >> 4) * 8;

    for (int it = 0; it < NIT; ++it) {
        CPWAIT2();
        __syncthreads();
        if (it + 3 < NIT) {
            int nst = it + 3, kA, kB; split_offs(nst, kA, kB);
            CPASYNC16(dA + (nst & 3)*ASTB64, aG + kA);
            uint32_t oB = dB + (nst & 3)*ASTB;
            CPASYNC16(oB,      bG + kB);
            CPASYNC16(oB + 16, bG + kB + 8);
        }
        CPCOMMIT();

        const uint32_t aS = sbA + (it & 3)*ASTB64;
        const uint32_t bS = sbB + (it & 3)*ASTB;
#pragma unroll
        for (int kk = 0; kk < 2; ++kk) {
            uint32_t af[2][4], br[2][4];
            const uint32_t cOff = (kk*16 + fcol) * 2;
#pragma unroll
            for (int mi = 0; mi < 2; mi++) {
                uint32_t ad = aS + (uint32_t)((wm*32 + mi*16 + frow) * 40) * 2 + cOff;
                LDSM4(af[mi][0], af[mi][1], af[mi][2], af[mi][3], ad);
            }
#pragma unroll
            for (int p = 0; p < 2; p++) {
                uint32_t bd = bS + (uint32_t)((wn*32 + p*16 + frow) * 40) * 2 + cOff;
                LDSM4(br[p][0], br[p][1], br[p][2], br[p][3], bd);
            }
#pragma unroll
            for (int mi = 0; mi < 2; mi++)
#pragma unroll
                for (int nj = 0; nj < 4; nj++) {
                    uint32_t bf[2] = { br[nj>>1][nj & 1], br[nj>>1][2 + (nj & 1)] };
                    MMA16816(acc[mi][nj], af[mi], bf);
                }
        }
    }

#pragma unroll
    for (int mi = 0; mi < 2; mi++) {
        int r = m0 + wm*32 + mi*16 + (lane >> 2);
#pragma unroll
        for (int nj = 0; nj < 4; nj++) {
            int cI = n0 + wn*32 + nj*8 + (lane & 3)*2;
            float b0v = bp[cI], b1v = bp[cI + 1];
            float2 v0 = { acc[mi][nj][0] + b0v, acc[mi][nj][1] + b1v };
            float2 v1 = { acc[mi][nj][2] + b0v, acc[mi][nj][3] + b1v };
            *reinterpret_cast<float2*>(out + (size_t)r * CC + cI)       = v0;
            *reinterpret_cast<float2*>(out + (size_t)(r + 8) * CC + cI) = v1;
        }
    }
}

// ------------------------- attention (fp32) ---------------------------------
__global__ __launch_bounds__(128) void attn_kernel(
    const float* __restrict__ relk, const float* __restrict__ relv,
    const int* __restrict__ pidx)
{
    const int id = blockIdx.x;              // b*T + s
    const int b  = id / TT_, s = id % TT_;
    const int lo = g_lo[id], hi = g_hi[id];
    const int L  = hi - lo;

    __shared__ float q_s[HH][DH];
    __shared__ float p_s[HH][TT_];
    __shared__ int   tok_sh[TT_];

    const int tid = threadIdx.x, lane = tid & 31, w = tid >> 5;
    const int tok_s = pidx[id];

    for (int i = tid; i < TT_; i += 128) tok_sh[i] = pidx[b * TT_ + i];
    for (int i = tid; i < HH*DH; i += 128)
        q_s[i >> 6][i & 63] = g_q0[(size_t)tok_s * 1536 + i];
    __syncthreads();

    const size_t rbase = ((size_t)(b*TT_ + s)) * TT_ * DH;

    for (int idx = w; idx < HH * L; idx += 4) {
        int h  = idx / L, tt = idx - h * L;
        int t  = lo + tt;
        const float* kp = g_q0 + (size_t)tok_sh[t] * 1536 + 512 + h * DH;
        const float* rp = relk + rbase + (size_t)t * DH;
        float a = q_s[h][lane]      * (kp[lane]      + rp[lane])
                + q_s[h][lane + 32] * (kp[lane + 32] + rp[lane + 32]);
#pragma unroll
        for (int o = 16; o; o >>= 1) a += __shfl_xor_sync(0xffffffffu, a, o);
        if (lane == 0) p_s[h][tt] = a * 0.125f;
    }
    __syncthreads();

#pragma unroll
    for (int hh = 0; hh < 2; hh++) {
        int h = 2*w + hh;
        float m = -1e30f;
        for (int tt = lane; tt < L; tt += 32) m = fmaxf(m, p_s[h][tt]);
#pragma unroll
        for (int o = 16; o; o >>= 1) m = fmaxf(m, __shfl_xor_sync(0xffffffffu, m, o));
        float sum = 0.f;
        for (int tt = lane; tt < L; tt += 32) {
            float e = __expf(p_s[h][tt] - m);
            p_s[h][tt] = e;
            sum += e;
        }
#pragma unroll
        for (int o = 16; o; o >>= 1) sum += __shfl_xor_sync(0xffffffffu, sum, o);
        float rinv = 1.0f / sum;

        float a0 = 0.f, a1 = 0.f;
        for (int tt = 0; tt < L; tt++) {
            int t = lo + tt;
            float p = p_s[h][tt];
            const float* vp = g_q0 + (size_t)tok_sh[t] * 1536 + 1024 + h * DH;
            const float* rp = relv + rbase + (size_t)t * DH;
            a0 += p * (vp[lane]      + rp[lane]);
            a1 += p * (vp[lane + 32] + rp[lane + 32]);
        }
        float o0 = a0 * rinv, o1 = a1 * rinv;
        size_t yb = (size_t)id * KEFF + h * DH;
        __nv_bfloat16 h0 = __float2bfloat16(o0);
        __nv_bfloat16 h1 = __float2bfloat16(o1);
        g_ys[yb + lane]            = h0;
        g_ys[yb + 512 + lane]      = __float2bfloat16(o0 - __bfloat162float(h0));
        g_ys[yb + lane + 32]       = h1;
        g_ys[yb + 512 + lane + 32] = __float2bfloat16(o1 - __bfloat162float(h1));
    }
}

// ---------------------------------------------------------------------------
extern "C" void kernel_launch(void* const* d_in, const int* in_sizes, int n_in,
                              void* d_out, int out_size)
{
    const float* x    = (const float*)d_in[0];
    const float* relk = (const float*)d_in[1];
    const float* relv = (const float*)d_in[2];
    const float* Wq   = (const float*)d_in[3];
    const float* bq   = (const float*)d_in[4];
    const float* Wk   = (const float*)d_in[5];
    const float* bk   = (const float*)d_in[6];
    const float* Wv   = (const float*)d_in[7];
    const float* bv   = (const float*)d_in[8];
    const float* Wp   = (const float*)d_in[9];
    const float* bp   = (const float*)d_in[10];
    const int*   pidx = (const int*)d_in[11];
    const int*   pb   = (const int*)d_in[12];
    const int*   inv  = (const int*)d_in[13];
    float*       out  = (float*)d_out;

    cudaFuncSetAttribute(qkv_mma, cudaFuncAttributeMaxDynamicSharedMemorySize, QKV_SMEM);
    cudaFuncSetAttribute(out_mma, cudaFuncAttributeMaxDynamicSharedMemorySize, OUT_SMEM);

    conv_all<<<(NTOK + 4*CC) * 128 / 256, 256>>>(x, Wq, Wk, Wv, Wp);
    seg_kernel<<<(MROWS + 255) / 256, 256>>>(pb);
    qkv_mma<<<dim3(16, 12), 256, QKV_SMEM>>>(bq, bk, bv);
    attn_kernel<<<MROWS, 128>>>(relk, relv, pidx);
    out_mma<<<dim3(32, 4), 256, OUT_SMEM>>>(bp, inv, out);
}